// round 2
// baseline (speedup 1.0000x reference)
#include <cuda_runtime.h>
#include <cuda_bf16.h>
#include <stdint.h>

// Problem constants
#define KS   16          // S
#define KN   1024        // N
#define KEPS 1e-7f

// Scratch: y[s][j][c][b] bf16 (16 MiB), base[s][i][b] fp32 (8 MiB)
__device__ __align__(16) __nv_bfloat16 g_y[(size_t)KS * KN * 512];
__device__ __align__(16) float         g_base[(size_t)KS * KN * 128];

// ---------------------------------------------------------------- helpers
static __device__ __forceinline__ uint32_t smem_u32(const void* p) {
    return (uint32_t)__cvta_generic_to_shared(p);
}
static __device__ __forceinline__ void ldsm_x4(uint32_t* r, uint32_t addr) {
    asm volatile("ldmatrix.sync.aligned.m8n8.x4.shared.b16 {%0,%1,%2,%3}, [%4];\n"
                 : "=r"(r[0]), "=r"(r[1]), "=r"(r[2]), "=r"(r[3]) : "r"(addr));
}
static __device__ __forceinline__ void ldsm_x4_t(uint32_t* r, uint32_t addr) {
    asm volatile("ldmatrix.sync.aligned.m8n8.x4.trans.shared.b16 {%0,%1,%2,%3}, [%4];\n"
                 : "=r"(r[0]), "=r"(r[1]), "=r"(r[2]), "=r"(r[3]) : "r"(addr));
}
static __device__ __forceinline__ void mma_bf16(float* d, const uint32_t* a,
                                                uint32_t b0, uint32_t b1) {
    asm volatile("mma.sync.aligned.m16n8k16.row.col.f32.bf16.bf16.f32 "
                 "{%0,%1,%2,%3}, {%4,%5,%6,%7}, {%8,%9}, {%0,%1,%2,%3};\n"
                 : "+f"(d[0]), "+f"(d[1]), "+f"(d[2]), "+f"(d[3])
                 : "r"(a[0]), "r"(a[1]), "r"(a[2]), "r"(a[3]), "r"(b0), "r"(b1));
}
static __device__ __forceinline__ uint32_t pack2(float lo, float hi) {
    uint16_t l = __bfloat16_as_ushort(__float2bfloat16_rn(lo));
    uint16_t h = __bfloat16_as_ushort(__float2bfloat16_rn(hi));
    return (uint32_t)l | ((uint32_t)h << 16);
}

// ================================================================ BASE (fp32)
// g_base[row, b] = sum_a x[row, a] * theta[a, b], full fp32 precision.
// Tile: 32 rows x 128 cols per block, 256 threads. K-tiles of 32.
__global__ __launch_bounds__(256) void base_kernel(
    const float* __restrict__ x, const float* __restrict__ th)
{
    __shared__ float Xs[32][33];
    __shared__ float Ts[32][128];

    const int tid  = threadIdx.x;
    const int tr   = tid >> 5;    // warp id 0..7: owns rows tr*4..tr*4+3
    const int tc   = tid & 31;    // lane: owns cols tc+32m, m<4
    const int row0 = blockIdx.x * 32;

    float acc[4][4];
#pragma unroll
    for (int i = 0; i < 4; i++)
#pragma unroll
        for (int m = 0; m < 4; m++) acc[i][m] = 0.f;

    for (int k0 = 0; k0 < 128; k0 += 32) {
        {   // Xs: 32 rows x 32 k = 256 float4s
            int r = tid >> 3, f = tid & 7;
            float4 v = *reinterpret_cast<const float4*>(
                x + (size_t)(row0 + r) * 128 + k0 + f * 4);
            Xs[r][f * 4 + 0] = v.x; Xs[r][f * 4 + 1] = v.y;
            Xs[r][f * 4 + 2] = v.z; Xs[r][f * 4 + 3] = v.w;
        }
#pragma unroll
        for (int q = 0; q < 4; q++) {   // Ts: 32 k x 128 = 1024 float4s
            int u  = tid + q * 256;
            int kk = u >> 5, cf = u & 31;
            *reinterpret_cast<float4*>(&Ts[kk][cf * 4]) =
                *reinterpret_cast<const float4*>(th + (size_t)(k0 + kk) * 128 + cf * 4);
        }
        __syncthreads();

#pragma unroll 8
        for (int kk = 0; kk < 32; kk++) {
            float xs[4], ts[4];
#pragma unroll
            for (int i = 0; i < 4; i++) xs[i] = Xs[tr * 4 + i][kk];
#pragma unroll
            for (int m = 0; m < 4; m++) ts[m] = Ts[kk][tc + 32 * m];
#pragma unroll
            for (int i = 0; i < 4; i++)
#pragma unroll
                for (int m = 0; m < 4; m++) acc[i][m] = fmaf(xs[i], ts[m], acc[i][m]);
        }
        __syncthreads();
    }

#pragma unroll
    for (int i = 0; i < 4; i++)
#pragma unroll
        for (int m = 0; m < 4; m++)
            g_base[(size_t)(row0 + tr * 4 + i) * 128 + tc + 32 * m] = acc[i][m];
}

// ================================================================ PREP (y, bf16 mma)
// g_y[row=(s*N+j), col=c*128+b] = sum_a x[row,a] * weight[a,b,c], bf16.
// GEMM: M=16384, K=128, Ncols=512.  Block 64x64 tile, 128 threads, 4 warps.
__global__ __launch_bounds__(128) void prep_kernel(
    const float* __restrict__ x, const float* __restrict__ w)
{
    __shared__ __nv_bfloat16 Xs[64][24];   // 16 k-cols used, pad->24
    __shared__ __nv_bfloat16 Ws[16][72];   // 64 n-cols used, pad->72

    const int tid  = threadIdx.x;
    const int lane = tid & 31;
    const int warp = tid >> 5;
    const int wm = warp >> 1;          // 0..1
    const int wn = warp & 1;           // 0..1
    const int row0 = blockIdx.x * 64;
    const int col0 = blockIdx.y * 64;

    float acc[2][4][4];
#pragma unroll
    for (int mi = 0; mi < 2; mi++)
#pragma unroll
        for (int ni = 0; ni < 4; ni++)
#pragma unroll
            for (int e = 0; e < 4; e++) acc[mi][ni][e] = 0.f;

    for (int a0 = 0; a0 < 128; a0 += 16) {
        // load X tile (64 rows x 16 k), fp32 -> bf16
#pragma unroll
        for (int q = 0; q < 2; q++) {
            int u  = tid + q * 128;      // 0..255 float4s
            int r  = u >> 2;
            int fo = u & 3;
            float4 v = *reinterpret_cast<const float4*>(
                x + (size_t)(row0 + r) * 128 + a0 + fo * 4);
            Xs[r][fo * 4 + 0] = __float2bfloat16_rn(v.x);
            Xs[r][fo * 4 + 1] = __float2bfloat16_rn(v.y);
            Xs[r][fo * 4 + 2] = __float2bfloat16_rn(v.z);
            Xs[r][fo * 4 + 3] = __float2bfloat16_rn(v.w);
        }
        // load W tile (16 k x 64 cols) via gather from weight
#pragma unroll
        for (int q = 0; q < 8; q++) {
            int u  = tid + q * 128;      // 0..1023
            int al = u >> 6;
            int cl = u & 63;
            int cg = col0 + cl;
            int a  = a0 + al;
            float v = w[(size_t)a * 512 + (size_t)(cg & 127) * 4 + (cg >> 7)];
            Ws[al][cl] = __float2bfloat16_rn(v);
        }
        __syncthreads();

        uint32_t af[2][4], bfr[2][4];
#pragma unroll
        for (int mi = 0; mi < 2; mi++)
            ldsm_x4(af[mi], smem_u32(&Xs[wm * 32 + mi * 16 + (lane & 15)][(lane >> 4) * 8]));
#pragma unroll
        for (int nh = 0; nh < 2; nh++)
            ldsm_x4_t(bfr[nh], smem_u32(&Ws[lane & 15][wn * 32 + nh * 16 + (lane >> 4) * 8]));
#pragma unroll
        for (int mi = 0; mi < 2; mi++)
#pragma unroll
            for (int ni = 0; ni < 4; ni++)
                mma_bf16(acc[mi][ni], af[mi],
                         bfr[ni >> 1][(ni & 1) * 2], bfr[ni >> 1][(ni & 1) * 2 + 1]);
        __syncthreads();
    }

    const int g  = lane >> 2;
    const int qc = lane & 3;
#pragma unroll
    for (int mi = 0; mi < 2; mi++)
#pragma unroll
        for (int ni = 0; ni < 4; ni++)
#pragma unroll
            for (int h = 0; h < 2; h++) {
                int r  = row0 + wm * 32 + mi * 16 + g + h * 8;
                int cg = col0 + wn * 32 + ni * 8 + qc * 2;
                *reinterpret_cast<uint32_t*>(&g_y[(size_t)r * 512 + cg]) =
                    pack2(acc[mi][ni][h * 2 + 0], acc[mi][ni][h * 2 + 1]);
            }
}

// ================================================================ MAIN
// Per block: s = blockIdx.y, i-tile of 64 rows. For c=0..3 keep separate
// fp32 accumulators (norm[i,c] applied in epilogue). Row-sums for norm are
// accumulated in fp32 by the loading thread (thread (i,c) owns all j).
__global__ __launch_bounds__(256) void main_kernel(
    const float* __restrict__ A, float* __restrict__ out)
{
    __shared__ __nv_bfloat16 As[4][64][24];    // [c][i][j0..15], row pad 24 (48B)
    __shared__ __nv_bfloat16 Ys[4][16][136];   // [c][j][b], row pad 136 (272B)
    __shared__ float inv_s[4][64];

    const int tid  = threadIdx.x;
    const int lane = tid & 31;
    const int warp = tid >> 5;
    const int wm = warp >> 2;     // 0..1 -> 32 i rows
    const int wn = warp & 3;      // 0..3 -> 32 b cols
    const int s  = blockIdx.y;
    const int i0 = blockIdx.x * 64;

    const int il = tid >> 2;      // 0..63 : i row this thread loads
    const int cc = tid & 3;       // 0..3  : channel this thread loads

    const float* Ap = A + ((size_t)(s * KN + i0 + il) * KN) * 5 + cc;
    const uint4* Yg = reinterpret_cast<const uint4*>(g_y + (size_t)s * KN * 512);

    float acc[4][2][4][4];
#pragma unroll
    for (int c = 0; c < 4; c++)
#pragma unroll
        for (int mi = 0; mi < 2; mi++)
#pragma unroll
            for (int ni = 0; ni < 4; ni++)
#pragma unroll
                for (int e = 0; e < 4; e++) acc[c][mi][ni][e] = 0.f;

    float rsum = 0.f;
    float av[16];
    uint4 yv[4];

    // prefetch k-tile 0
#pragma unroll
    for (int j = 0; j < 16; j++) av[j] = __ldg(Ap + (size_t)j * 5);
#pragma unroll
    for (int q = 0; q < 4; q++) yv[q] = Yg[tid + q * 256];

    for (int kt = 0; kt < 64; kt++) {
        // fp32 row-sum contribution + bf16 pack into smem
#pragma unroll
        for (int j = 0; j < 16; j++) rsum += av[j];
        uint32_t* arow = reinterpret_cast<uint32_t*>(&As[cc][il][0]);
#pragma unroll
        for (int p = 0; p < 8; p++) arow[p] = pack2(av[2 * p], av[2 * p + 1]);
#pragma unroll
        for (int q = 0; q < 4; q++) {
            int u  = tid + q * 256;       // 0..1023 uint4s of the y k-tile
            int j  = u >> 6;
            int rm = u & 63;
            *reinterpret_cast<uint4*>(&Ys[rm >> 4][j][(rm & 15) * 8]) = yv[q];
        }
        __syncthreads();

        // prefetch next k-tile (overlaps with mma below)
        if (kt + 1 < 64) {
            size_t jb = (size_t)(kt + 1) * 16;
#pragma unroll
            for (int j = 0; j < 16; j++) av[j] = __ldg(Ap + (jb + j) * 5);
#pragma unroll
            for (int q = 0; q < 4; q++) yv[q] = Yg[(kt + 1) * 1024 + tid + q * 256];
        }

        // tensor-core compute: 4 channels x (2 m-tiles x 4 n-tiles)
#pragma unroll
        for (int c = 0; c < 4; c++) {
            uint32_t af[2][4], bfr[2][4];
#pragma unroll
            for (int mi = 0; mi < 2; mi++)
                ldsm_x4(af[mi], smem_u32(&As[c][wm * 32 + mi * 16 + (lane & 15)][(lane >> 4) * 8]));
#pragma unroll
            for (int nh = 0; nh < 2; nh++)
                ldsm_x4_t(bfr[nh], smem_u32(&Ys[c][lane & 15][wn * 32 + nh * 16 + (lane >> 4) * 8]));
#pragma unroll
            for (int mi = 0; mi < 2; mi++)
#pragma unroll
                for (int ni = 0; ni < 4; ni++)
                    mma_bf16(acc[c][mi][ni], af[mi],
                             bfr[ni >> 1][(ni & 1) * 2], bfr[ni >> 1][(ni & 1) * 2 + 1]);
        }
        __syncthreads();
    }

    // norm = 1/(rowsum + eps): thread (il,cc) owns exactly one (i,c) sum
    inv_s[cc][il] = 1.0f / (rsum + KEPS);
    __syncthreads();

    const int g  = lane >> 2;
    const int qc = lane & 3;
#pragma unroll
    for (int mi = 0; mi < 2; mi++)
#pragma unroll
        for (int h = 0; h < 2; h++) {
            const int rl = wm * 32 + mi * 16 + g + h * 8;
            float iv[4];
#pragma unroll
            for (int c = 0; c < 4; c++) iv[c] = inv_s[c][rl];
#pragma unroll
            for (int ni = 0; ni < 4; ni++) {
                const int b = wn * 32 + ni * 8 + qc * 2;
                float v0 = 0.f, v1 = 0.f;
#pragma unroll
                for (int c = 0; c < 4; c++) {
                    v0 = fmaf(acc[c][mi][ni][h * 2 + 0], iv[c], v0);
                    v1 = fmaf(acc[c][mi][ni][h * 2 + 1], iv[c], v1);
                }
                const size_t o = (size_t)(s * KN + i0 + rl) * 128 + b;
                v0 += g_base[o];
                v1 += g_base[o + 1];
                out[o]     = tanhf(v0);
                out[o + 1] = tanhf(v1);
            }
        }
}

// ================================================================ launch
extern "C" void kernel_launch(void* const* d_in, const int* in_sizes, int n_in,
                              void* d_out, int out_size) {
    const float* A  = (const float*)d_in[0];
    const float* x  = (const float*)d_in[1];
    const float* w  = (const float*)d_in[2];
    const float* th = (const float*)d_in[3];
    float* out = (float*)d_out;
    (void)in_sizes; (void)n_in; (void)out_size;

    base_kernel<<<512, 256>>>(x, th);
    prep_kernel<<<dim3(256, 8), 128>>>(x, w);
    main_kernel<<<dim3(16, 16), 256>>>(A, out);
}

// round 4
// speedup vs baseline: 1.1340x; 1.1340x over previous
#include <cuda_runtime.h>
#include <cuda_bf16.h>
#include <stdint.h>

// Problem constants
#define KS   16          // S
#define KN   1024        // N
#define KEPS 1e-7f

// Scratch: y[s][j][c][b] bf16 (16 MiB), base[s][i][b] fp32 (8 MiB)
__device__ __align__(16) __nv_bfloat16 g_y[(size_t)KS * KN * 512];
__device__ __align__(16) float         g_base[(size_t)KS * KN * 128];

// ---------------------------------------------------------------- helpers
static __device__ __forceinline__ uint32_t smem_u32(const void* p) {
    return (uint32_t)__cvta_generic_to_shared(p);
}
static __device__ __forceinline__ void ldsm_x4(uint32_t* r, uint32_t addr) {
    asm volatile("ldmatrix.sync.aligned.m8n8.x4.shared.b16 {%0,%1,%2,%3}, [%4];\n"
                 : "=r"(r[0]), "=r"(r[1]), "=r"(r[2]), "=r"(r[3]) : "r"(addr));
}
static __device__ __forceinline__ void ldsm_x4_t(uint32_t* r, uint32_t addr) {
    asm volatile("ldmatrix.sync.aligned.m8n8.x4.trans.shared.b16 {%0,%1,%2,%3}, [%4];\n"
                 : "=r"(r[0]), "=r"(r[1]), "=r"(r[2]), "=r"(r[3]) : "r"(addr));
}
static __device__ __forceinline__ void mma_bf16(float* d, const uint32_t* a,
                                                uint32_t b0, uint32_t b1) {
    asm volatile("mma.sync.aligned.m16n8k16.row.col.f32.bf16.bf16.f32 "
                 "{%0,%1,%2,%3}, {%4,%5,%6,%7}, {%8,%9}, {%0,%1,%2,%3};\n"
                 : "+f"(d[0]), "+f"(d[1]), "+f"(d[2]), "+f"(d[3])
                 : "r"(a[0]), "r"(a[1]), "r"(a[2]), "r"(a[3]), "r"(b0), "r"(b1));
}
// pack (lo, hi) floats into one bf16x2 register, single instruction
static __device__ __forceinline__ uint32_t pack2f(float lo, float hi) {
    uint32_t d;
    asm("cvt.rn.bf16x2.f32 %0, %1, %2;\n" : "=r"(d) : "f"(hi), "f"(lo));
    return d;
}
static __device__ __forceinline__ uint32_t pack2(float lo, float hi) {
    return pack2f(lo, hi);
}

// ================================================================ BASE (fp32)
// g_base[row, b] = sum_a x[row, a] * theta[a, b], full fp32 precision.
// Tile: 64 rows x 128 cols per block, 256 threads (8 warps x 8 rows each).
__global__ __launch_bounds__(256) void base_kernel(
    const float* __restrict__ x, const float* __restrict__ th)
{
    __shared__ float Xs[64][32];
    __shared__ float Ts[32][128];

    const int tid  = threadIdx.x;
    const int lane = tid & 31;
    const int tr   = tid >> 5;    // warp id 0..7: owns rows tr*8..tr*8+7
    const int row0 = blockIdx.x * 64;

    float acc[8][4];
#pragma unroll
    for (int i = 0; i < 8; i++)
#pragma unroll
        for (int m = 0; m < 4; m++) acc[i][m] = 0.f;

    for (int k0 = 0; k0 < 128; k0 += 32) {
        // Xs: 64 rows x 32 k = 512 float4s, 2 per thread
#pragma unroll
        for (int q = 0; q < 2; q++) {
            int u = tid + q * 256;
            int r = u >> 3, f = u & 7;
            *reinterpret_cast<float4*>(&Xs[r][f * 4]) =
                *reinterpret_cast<const float4*>(x + (size_t)(row0 + r) * 128 + k0 + f * 4);
        }
        // Ts: 32 k x 128 = 1024 float4s, 4 per thread
#pragma unroll
        for (int q = 0; q < 4; q++) {
            int u  = tid + q * 256;
            int kk = u >> 5, cf = u & 31;
            *reinterpret_cast<float4*>(&Ts[kk][cf * 4]) =
                *reinterpret_cast<const float4*>(th + (size_t)(k0 + kk) * 128 + cf * 4);
        }
        __syncthreads();

#pragma unroll 4
        for (int kk = 0; kk < 32; kk++) {
            float ts[4];
#pragma unroll
            for (int m = 0; m < 4; m++) ts[m] = Ts[kk][lane + 32 * m];
#pragma unroll
            for (int i = 0; i < 8; i++) {
                float xs = Xs[tr * 8 + i][kk];
#pragma unroll
                for (int m = 0; m < 4; m++) acc[i][m] = fmaf(xs, ts[m], acc[i][m]);
            }
        }
        __syncthreads();
    }

#pragma unroll
    for (int i = 0; i < 8; i++)
#pragma unroll
        for (int m = 0; m < 4; m++)
            g_base[(size_t)(row0 + tr * 8 + i) * 128 + lane + 32 * m] = acc[i][m];
}

// ================================================================ PREP (y, bf16 mma)
// g_y[row=(s*N+j), col=c*128+b] = sum_a x[row,a] * weight[a,b,c], bf16.
// GEMM: M=16384, K=128, Ncols=512.  Block 64x64 tile, 128 threads, 4 warps.
__global__ __launch_bounds__(128) void prep_kernel(
    const float* __restrict__ x, const float* __restrict__ w)
{
    __shared__ __nv_bfloat16 Xs[64][24];   // 16 k-cols used, pad->24
    __shared__ __nv_bfloat16 Ws[16][72];   // 64 n-cols used, pad->72

    const int tid  = threadIdx.x;
    const int lane = tid & 31;
    const int warp = tid >> 5;
    const int wm = warp >> 1;          // 0..1
    const int wn = warp & 1;           // 0..1
    const int row0 = blockIdx.x * 64;
    const int col0 = blockIdx.y * 64;

    float acc[2][4][4];
#pragma unroll
    for (int mi = 0; mi < 2; mi++)
#pragma unroll
        for (int ni = 0; ni < 4; ni++)
#pragma unroll
            for (int e = 0; e < 4; e++) acc[mi][ni][e] = 0.f;

    for (int a0 = 0; a0 < 128; a0 += 16) {
        // load X tile (64 rows x 16 k), fp32 -> bf16
#pragma unroll
        for (int q = 0; q < 2; q++) {
            int u  = tid + q * 128;      // 0..255 float4s
            int r  = u >> 2;
            int fo = u & 3;
            float4 v = *reinterpret_cast<const float4*>(
                x + (size_t)(row0 + r) * 128 + a0 + fo * 4);
            *reinterpret_cast<uint32_t*>(&Xs[r][fo * 4 + 0]) = pack2f(v.x, v.y);
            *reinterpret_cast<uint32_t*>(&Xs[r][fo * 4 + 2]) = pack2f(v.z, v.w);
        }
        // load W tile (16 k x 64 cols) via gather from weight
#pragma unroll
        for (int q = 0; q < 8; q++) {
            int u  = tid + q * 128;      // 0..1023
            int al = u >> 6;
            int cl = u & 63;
            int cg = col0 + cl;
            int a  = a0 + al;
            float v = w[(size_t)a * 512 + (size_t)(cg & 127) * 4 + (cg >> 7)];
            Ws[al][cl] = __float2bfloat16_rn(v);
        }
        __syncthreads();

        uint32_t af[2][4], bfr[2][4];
#pragma unroll
        for (int mi = 0; mi < 2; mi++)
            ldsm_x4(af[mi], smem_u32(&Xs[wm * 32 + mi * 16 + (lane & 15)][(lane >> 4) * 8]));
#pragma unroll
        for (int nh = 0; nh < 2; nh++)
            ldsm_x4_t(bfr[nh], smem_u32(&Ws[lane & 15][wn * 32 + nh * 16 + (lane >> 4) * 8]));
#pragma unroll
        for (int mi = 0; mi < 2; mi++)
#pragma unroll
            for (int ni = 0; ni < 4; ni++)
                mma_bf16(acc[mi][ni], af[mi],
                         bfr[ni >> 1][(ni & 1) * 2], bfr[ni >> 1][(ni & 1) * 2 + 1]);
        __syncthreads();
    }

    const int g  = lane >> 2;
    const int qc = lane & 3;
#pragma unroll
    for (int mi = 0; mi < 2; mi++)
#pragma unroll
        for (int ni = 0; ni < 4; ni++)
#pragma unroll
            for (int h = 0; h < 2; h++) {
                int r  = row0 + wm * 32 + mi * 16 + g + h * 8;
                int cg = col0 + wn * 32 + ni * 8 + qc * 2;
                *reinterpret_cast<uint32_t*>(&g_y[(size_t)r * 512 + cg]) =
                    pack2(acc[mi][ni][h * 2 + 0], acc[mi][ni][h * 2 + 1]);
            }
}

// ================================================================ MAIN
// Per block: s = blockIdx.y, i-tile of 64 rows x 128 b cols.
// A loaded with vector LDG.128: thread owns (row il, j-group jg of 4 js, all
// 5 channels) = 5 uint4 per k-tile -> high MLP. Channel deinterleave + bf16
// pack in registers (cvt.rn.bf16x2.f32). Row sums exact fp32, reduced over
// the 4 jg lanes via shfl. 4 c-channel fp32 mma accumulators, norm applied
// in epilogue.
__global__ __launch_bounds__(256) void main_kernel(
    const float* __restrict__ A, float* __restrict__ out)
{
    __shared__ __nv_bfloat16 As[4][64][24];    // [c][i][j0..15], row pad 24 (48B)
    __shared__ __nv_bfloat16 Ys[4][16][136];   // [c][j][b], row pad 136 (272B)
    __shared__ float inv_s[4][64];

    const int tid  = threadIdx.x;
    const int lane = tid & 31;
    const int warp = tid >> 5;
    const int wm = warp >> 2;     // 0..1 -> 32 i rows
    const int wn = warp & 3;      // 0..3 -> 32 b cols
    const int s  = blockIdx.y;
    const int i0 = blockIdx.x * 64;

    const int il = tid >> 2;      // 0..63 : i row this thread loads
    const int jg = tid & 3;       // 0..3  : j-group (4 js) within the 16-j k-tile

    // A row base: floats. Offsets stay 16B aligned (20 floats per jg).
    const float* Ap = A + (size_t)(s * KN + i0 + il) * (KN * 5) + jg * 20;
    const uint4* Yg = reinterpret_cast<const uint4*>(g_y + (size_t)s * KN * 512);

    float acc[4][2][4][4];
#pragma unroll
    for (int c = 0; c < 4; c++)
#pragma unroll
        for (int mi = 0; mi < 2; mi++)
#pragma unroll
            for (int ni = 0; ni < 4; ni++)
#pragma unroll
                for (int e = 0; e < 4; e++) acc[c][mi][ni][e] = 0.f;

    float rs[4] = {0.f, 0.f, 0.f, 0.f};
    uint4 qv[5];
    uint4 yv[4];

    // prefetch k-tile 0
#pragma unroll
    for (int p = 0; p < 5; p++) qv[p] = __ldcs(reinterpret_cast<const uint4*>(Ap) + p);
#pragma unroll
    for (int q = 0; q < 4; q++) yv[q] = Yg[tid + q * 256];

    for (int kt = 0; kt < 64; kt++) {
        // deinterleave 20 floats = 4 js x 5 channels; c=4 dropped
        float fa[20];
#pragma unroll
        for (int p = 0; p < 5; p++) {
            fa[p * 4 + 0] = __uint_as_float(qv[p].x);
            fa[p * 4 + 1] = __uint_as_float(qv[p].y);
            fa[p * 4 + 2] = __uint_as_float(qv[p].z);
            fa[p * 4 + 3] = __uint_as_float(qv[p].w);
        }
#pragma unroll
        for (int c = 0; c < 4; c++) {
            // fp32 row-sum contribution (exact)
            rs[c] += (fa[c] + fa[5 + c]) + (fa[10 + c] + fa[15 + c]);
            // bf16 pack: halves [j0,j1] and [j2,j3]
            uint2 v;
            v.x = pack2f(fa[c],      fa[5 + c]);
            v.y = pack2f(fa[10 + c], fa[15 + c]);
            *reinterpret_cast<uint2*>(&As[c][il][jg * 4]) = v;
        }
#pragma unroll
        for (int q = 0; q < 4; q++) {
            int u  = tid + q * 256;       // 0..1023 uint4s of the y k-tile
            int j  = u >> 6;
            int rm = u & 63;
            *reinterpret_cast<uint4*>(&Ys[rm >> 4][j][(rm & 15) * 8]) = yv[q];
        }
        __syncthreads();

        // prefetch next k-tile (in flight during the mma section below)
        if (kt + 1 < 64) {
            const uint4* An = reinterpret_cast<const uint4*>(Ap + (size_t)(kt + 1) * 80);
#pragma unroll
            for (int p = 0; p < 5; p++) qv[p] = __ldcs(An + p);
#pragma unroll
            for (int q = 0; q < 4; q++) yv[q] = Yg[(kt + 1) * 1024 + tid + q * 256];
        }

        // tensor-core compute: 4 channels x (2 m-tiles x 4 n-tiles)
#pragma unroll
        for (int c = 0; c < 4; c++) {
            uint32_t af[2][4], bfr[2][4];
#pragma unroll
            for (int mi = 0; mi < 2; mi++)
                ldsm_x4(af[mi], smem_u32(&As[c][wm * 32 + mi * 16 + (lane & 15)][(lane >> 4) * 8]));
#pragma unroll
            for (int nh = 0; nh < 2; nh++)
                ldsm_x4_t(bfr[nh], smem_u32(&Ys[c][lane & 15][wn * 32 + nh * 16 + (lane >> 4) * 8]));
#pragma unroll
            for (int mi = 0; mi < 2; mi++)
#pragma unroll
                for (int ni = 0; ni < 4; ni++)
                    mma_bf16(acc[c][mi][ni], af[mi],
                             bfr[ni >> 1][(ni & 1) * 2], bfr[ni >> 1][(ni & 1) * 2 + 1]);
        }
        __syncthreads();
    }

    // reduce row sums over the 4 jg lanes (lane bits 0-1), then invert
#pragma unroll
    for (int c = 0; c < 4; c++) {
        rs[c] += __shfl_xor_sync(0xFFFFFFFFu, rs[c], 1);
        rs[c] += __shfl_xor_sync(0xFFFFFFFFu, rs[c], 2);
    }
    if (jg == 0) {
#pragma unroll
        for (int c = 0; c < 4; c++) inv_s[c][il] = 1.0f / (rs[c] + KEPS);
    }
    __syncthreads();

    const int g  = lane >> 2;
    const int qc = lane & 3;
#pragma unroll
    for (int mi = 0; mi < 2; mi++)
#pragma unroll
        for (int h = 0; h < 2; h++) {
            const int rl = wm * 32 + mi * 16 + g + h * 8;
            float iv[4];
#pragma unroll
            for (int c = 0; c < 4; c++) iv[c] = inv_s[c][rl];
#pragma unroll
            for (int ni = 0; ni < 4; ni++) {
                const int b = wn * 32 + ni * 8 + qc * 2;
                float v0 = 0.f, v1 = 0.f;
#pragma unroll
                for (int c = 0; c < 4; c++) {
                    v0 = fmaf(acc[c][mi][ni][h * 2 + 0], iv[c], v0);
                    v1 = fmaf(acc[c][mi][ni][h * 2 + 1], iv[c], v1);
                }
                const size_t o = (size_t)(s * KN + i0 + rl) * 128 + b;
                v0 += g_base[o];
                v1 += g_base[o + 1];
                out[o]     = tanhf(v0);
                out[o + 1] = tanhf(v1);
            }
        }
}

// ================================================================ launch
extern "C" void kernel_launch(void* const* d_in, const int* in_sizes, int n_in,
                              void* d_out, int out_size) {
    const float* A  = (const float*)d_in[0];
    const float* x  = (const float*)d_in[1];
    const float* w  = (const float*)d_in[2];
    const float* th = (const float*)d_in[3];
    float* out = (float*)d_out;
    (void)in_sizes; (void)n_in; (void)out_size;

    base_kernel<<<256, 256>>>(x, th);
    prep_kernel<<<dim3(256, 8), 128>>>(x, w);
    main_kernel<<<dim3(16, 16), 256>>>(A, out);
}

// round 10
// speedup vs baseline: 1.4072x; 1.2410x over previous
#include <cuda_runtime.h>
#include <cuda_bf16.h>
#include <stdint.h>

// Problem constants
#define KS   16          // S
#define KN   1024        // N
#define KEPS 1e-7f

// Scratch: y[s][j][c*128+b] bf16 (16 MiB), base[s][i][b] fp32 (8 MiB)
__device__ __align__(16) __nv_bfloat16 g_y[(size_t)KS * KN * 512];
__device__ __align__(16) float         g_base[(size_t)KS * KN * 128];

// ---------------------------------------------------------------- helpers
static __device__ __forceinline__ uint32_t smem_u32(const void* p) {
    return (uint32_t)__cvta_generic_to_shared(p);
}
static __device__ __forceinline__ void ldsm_x4(uint32_t* r, uint32_t addr) {
    asm volatile("ldmatrix.sync.aligned.m8n8.x4.shared.b16 {%0,%1,%2,%3}, [%4];\n"
                 : "=r"(r[0]), "=r"(r[1]), "=r"(r[2]), "=r"(r[3]) : "r"(addr));
}
static __device__ __forceinline__ void ldsm_x4_t(uint32_t* r, uint32_t addr) {
    asm volatile("ldmatrix.sync.aligned.m8n8.x4.trans.shared.b16 {%0,%1,%2,%3}, [%4];\n"
                 : "=r"(r[0]), "=r"(r[1]), "=r"(r[2]), "=r"(r[3]) : "r"(addr));
}
static __device__ __forceinline__ void mma_bf16(float* d, const uint32_t* a,
                                                uint32_t b0, uint32_t b1) {
    asm volatile("mma.sync.aligned.m16n8k16.row.col.f32.bf16.bf16.f32 "
                 "{%0,%1,%2,%3}, {%4,%5,%6,%7}, {%8,%9}, {%0,%1,%2,%3};\n"
                 : "+f"(d[0]), "+f"(d[1]), "+f"(d[2]), "+f"(d[3])
                 : "r"(a[0]), "r"(a[1]), "r"(a[2]), "r"(a[3]), "r"(b0), "r"(b1));
}
static __device__ __forceinline__ uint32_t pack2f(float lo, float hi) {
    uint32_t d;
    asm("cvt.rn.bf16x2.f32 %0, %1, %2;\n" : "=r"(d) : "f"(hi), "f"(lo));
    return d;
}
static __device__ __forceinline__ void cp_async16(uint32_t dst, const void* src) {
    asm volatile("cp.async.cg.shared.global [%0], [%1], 16;\n"
                 :: "r"(dst), "l"(src) : "memory");
}
#define CP_COMMIT() asm volatile("cp.async.commit_group;\n" ::: "memory")
template <int N>
static __device__ __forceinline__ void cp_wait() {
    asm volatile("cp.async.wait_group %0;\n" :: "n"(N) : "memory");
}

// ================================================================ AUX (fused)
// Blocks [0, 1024): prep  — g_y[row=(s*N+j), cb=c*128+b] = sum_a x[row,a]*w[a,b,c]
//                   (bf16 mma, 64-row x 128-cb tile, 8 warps)
// Blocks [1024, 1280): base — g_base = x @ theta, full fp32 SIMT
//                   (64-row tile, 8 warps x 8 rows)
// Both parts: 256 threads. Concurrency hides prep under FFMA-bound base.
__global__ __launch_bounds__(256) void aux_kernel(
    const float* __restrict__ x, const float* __restrict__ w,
    const float* __restrict__ th)
{
    const int tid  = threadIdx.x;
    const int lane = tid & 31;
    const int warp = tid >> 5;

    if (blockIdx.x < 1024) {
        // ---------------- PREP ----------------
        __shared__ __nv_bfloat16 Xs[64][24];    // [j][a(16)], pad->24
        __shared__ __nv_bfloat16 Ws[16][136];   // [a][cb(128)], pad->136

        const int wm = warp >> 2;           // 0..1 -> 32 j rows
        const int wn = warp & 3;            // 0..3 -> 32 cb cols
        const int row0 = (blockIdx.x >> 2) * 64;
        const int col0 = (blockIdx.x & 3) * 128;

        float acc[2][4][4];
#pragma unroll
        for (int mi = 0; mi < 2; mi++)
#pragma unroll
            for (int ni = 0; ni < 4; ni++)
#pragma unroll
                for (int e = 0; e < 4; e++) acc[mi][ni][e] = 0.f;

        for (int a0 = 0; a0 < 128; a0 += 16) {
            {   // X tile: 64 rows x 16 a = 256 float4s, 1 per thread
                int r = tid >> 2, fo = tid & 3;
                float4 v = *reinterpret_cast<const float4*>(
                    x + (size_t)(row0 + r) * 128 + a0 + fo * 4);
                *reinterpret_cast<uint32_t*>(&Xs[r][fo * 4 + 0]) = pack2f(v.x, v.y);
                *reinterpret_cast<uint32_t*>(&Xs[r][fo * 4 + 2]) = pack2f(v.z, v.w);
            }
            // W tile: 16 a x 128 cb, gather (cb = c*128+b -> w[a*512 + b*4 + c])
#pragma unroll
            for (int q = 0; q < 8; q++) {
                int u  = tid + q * 256;
                int al = u >> 7;
                int cl = u & 127;
                int cg = col0 + cl;
                Ws[al][cl] = __float2bfloat16_rn(
                    w[(size_t)(a0 + al) * 512 + (size_t)(cg & 127) * 4 + (cg >> 7)]);
            }
            __syncthreads();

            uint32_t af[2][4], bfr[2][4];
#pragma unroll
            for (int mi = 0; mi < 2; mi++)
                ldsm_x4(af[mi], smem_u32(&Xs[wm * 32 + mi * 16 + (lane & 15)][(lane >> 4) * 8]));
#pragma unroll
            for (int nh = 0; nh < 2; nh++)
                ldsm_x4_t(bfr[nh], smem_u32(&Ws[lane & 15][wn * 32 + nh * 16 + (lane >> 4) * 8]));
#pragma unroll
            for (int mi = 0; mi < 2; mi++)
#pragma unroll
                for (int ni = 0; ni < 4; ni++)
                    mma_bf16(acc[mi][ni], af[mi],
                             bfr[ni >> 1][(ni & 1) * 2], bfr[ni >> 1][(ni & 1) * 2 + 1]);
            __syncthreads();
        }

        const int g  = lane >> 2;
        const int qc = lane & 3;
#pragma unroll
        for (int mi = 0; mi < 2; mi++)
#pragma unroll
            for (int ni = 0; ni < 4; ni++)
#pragma unroll
                for (int h = 0; h < 2; h++) {
                    int r  = row0 + wm * 32 + mi * 16 + g + h * 8;
                    int cg = col0 + wn * 32 + ni * 8 + qc * 2;
                    *reinterpret_cast<uint32_t*>(&g_y[(size_t)r * 512 + cg]) =
                        pack2f(acc[mi][ni][h * 2 + 0], acc[mi][ni][h * 2 + 1]);
                }
    } else {
        // ---------------- BASE (fp32 exact) ----------------
        __shared__ float Xf[64][32];
        __shared__ float Ts[32][128];

        const int tr   = warp;              // 8 warps x 8 rows
        const int row0 = (blockIdx.x - 1024) * 64;

        float acc[8][4];
#pragma unroll
        for (int i = 0; i < 8; i++)
#pragma unroll
            for (int m = 0; m < 4; m++) acc[i][m] = 0.f;

        for (int k0 = 0; k0 < 128; k0 += 32) {
#pragma unroll
            for (int q = 0; q < 2; q++) {
                int u = tid + q * 256;
                int r = u >> 3, f = u & 7;
                *reinterpret_cast<float4*>(&Xf[r][f * 4]) =
                    *reinterpret_cast<const float4*>(x + (size_t)(row0 + r) * 128 + k0 + f * 4);
            }
#pragma unroll
            for (int q = 0; q < 4; q++) {
                int u  = tid + q * 256;
                int kk = u >> 5, cf = u & 31;
                *reinterpret_cast<float4*>(&Ts[kk][cf * 4]) =
                    *reinterpret_cast<const float4*>(th + (size_t)(k0 + kk) * 128 + cf * 4);
            }
            __syncthreads();

#pragma unroll 4
            for (int kk = 0; kk < 32; kk++) {
                float ts[4];
#pragma unroll
                for (int m = 0; m < 4; m++) ts[m] = Ts[kk][lane + 32 * m];
#pragma unroll
                for (int i = 0; i < 8; i++) {
                    float xs = Xf[tr * 8 + i][kk];
#pragma unroll
                    for (int m = 0; m < 4; m++) acc[i][m] = fmaf(xs, ts[m], acc[i][m]);
                }
            }
            __syncthreads();
        }

#pragma unroll
        for (int i = 0; i < 8; i++)
#pragma unroll
            for (int m = 0; m < 4; m++)
                g_base[(size_t)(row0 + tr * 8 + i) * 128 + lane + 32 * m] = acc[i][m];
    }
}

// ================================================================ MAIN
// 512 threads, 64 i-rows x 128 b per CTA, k-tile = 32 j. 16 warps, 4/SMSP.
// Per-thread mma accumulators: 4c x (2m x 2n8) x 4 = 64 regs.
// A: register prefetch (5 x LDG.128/thread/iter), convert fp32->bf16 + exact
//    fp32 rowsums in flight. Y: cp.async 16B into double-buffered smem stage.
// smem (dynamic):
//   As   4c x 64i x (32j pad->40) bf16 = 20480 B      (single buffer)
//   Ys   2 stages x 4c x 32j x (128b pad->136) bf16 = 69632 B
//   inv  4c x 64 fp32 = 1024 B
#define AS_OFF   0
#define YS_OFF   20480
#define YS_STG   34816
#define INV_OFF  90112
#define SMEM_TOT 91136

static __device__ __forceinline__ uint32_t ys_off(int stage, int c, int j, int b) {
    return YS_OFF + stage * YS_STG + (((c * 32 + j) * 136) + b) * 2;
}

__global__ __launch_bounds__(512, 1) void main_kernel(
    const float* __restrict__ A, float* __restrict__ out)
{
    extern __shared__ char smem[];
    const uint32_t sb = smem_u32(smem);

    const int tid  = threadIdx.x;
    const int lane = tid & 31;
    const int warp = tid >> 5;
    const int wm = warp >> 3;     // 0..1 -> 32 i rows
    const int wn = warp & 7;      // 0..7 -> 16 b cols
    const int s  = blockIdx.y;
    const int i0 = blockIdx.x * 64;

    const int il = tid >> 3;      // 0..63 : i row this thread converts
    const int jg = tid & 7;       // 0..7  : j-group of 4 within the 32-j k-tile

    const float* Ap = A + (size_t)(s * KN + i0 + il) * 5120 + jg * 20;

    float acc[4][2][2][4];
#pragma unroll
    for (int c = 0; c < 4; c++)
#pragma unroll
        for (int mi = 0; mi < 2; mi++)
#pragma unroll
            for (int ni = 0; ni < 2; ni++)
#pragma unroll
                for (int e = 0; e < 4; e++) acc[c][mi][ni][e] = 0.f;

    float rs[4] = {0.f, 0.f, 0.f, 0.f};
    uint4 qa[5];

    // prime: A regs for kt=0, Y stage 0
#pragma unroll
    for (int p = 0; p < 5; p++) qa[p] = __ldcs(reinterpret_cast<const uint4*>(Ap) + p);
#pragma unroll
    for (int q = 0; q < 4; q++) {
        int u = tid + q * 512;
        int j = u >> 6, rem = u & 63;
        int c = rem >> 4, bq = rem & 15;
        cp_async16(sb + ys_off(0, c, j, bq * 8),
                   g_y + (size_t)(s * KN + j) * 512 + c * 128 + bq * 8);
    }
    CP_COMMIT();

    for (int kt = 0; kt < 32; kt++) {
        // ---- convert + store A(kt): 4 j x 5 c -> rowsums + bf16 smem ----
        float f[20];
#pragma unroll
        for (int p = 0; p < 5; p++) {
            f[p * 4 + 0] = __uint_as_float(qa[p].x);
            f[p * 4 + 1] = __uint_as_float(qa[p].y);
            f[p * 4 + 2] = __uint_as_float(qa[p].z);
            f[p * 4 + 3] = __uint_as_float(qa[p].w);
        }
#pragma unroll
        for (int c = 0; c < 4; c++) {
            rs[c] += (f[c] + f[5 + c]) + (f[10 + c] + f[15 + c]);
            uint2 v;
            v.x = pack2f(f[c],      f[5 + c]);
            v.y = pack2f(f[10 + c], f[15 + c]);
            // As[c][il][jg*4], pitch 40 bf16 (80 B)
            *reinterpret_cast<uint2*>(smem + AS_OFF + (c * 64 + il) * 80 + jg * 8) = v;
        }

        // ---- issue next-iter loads, then drain current Y group ----
        if (kt + 1 < 32) {
#pragma unroll
            for (int q = 0; q < 4; q++) {
                int u = tid + q * 512;
                int j = u >> 6, rem = u & 63;
                int c = rem >> 4, bq = rem & 15;
                cp_async16(sb + ys_off((kt + 1) & 1, c, j, bq * 8),
                           g_y + (size_t)(s * KN + (kt + 1) * 32 + j) * 512 + c * 128 + bq * 8);
            }
            CP_COMMIT();
            const uint4* an = reinterpret_cast<const uint4*>(Ap + (size_t)(kt + 1) * 160);
#pragma unroll
            for (int p = 0; p < 5; p++) qa[p] = __ldcs(an + p);
            cp_wait<1>();
        } else {
            cp_wait<0>();
        }
        __syncthreads();

        // ---- mma: 4c x 2 ksteps x (2m x 2n8) ----
        const int stage = kt & 1;
#pragma unroll
        for (int c = 0; c < 4; c++) {
#pragma unroll
            for (int ks = 0; ks < 2; ks++) {
                uint32_t af[2][4], bfr[4];
#pragma unroll
                for (int mi = 0; mi < 2; mi++)
                    ldsm_x4(af[mi], sb + AS_OFF
                            + (c * 64 + wm * 32 + mi * 16 + (lane & 15)) * 80
                            + (ks * 16 + (lane >> 4) * 8) * 2);
                ldsm_x4_t(bfr, sb + ys_off(stage, c, ks * 16 + (lane & 15),
                                           wn * 16 + (lane >> 4) * 8));
#pragma unroll
                for (int mi = 0; mi < 2; mi++)
#pragma unroll
                    for (int ni = 0; ni < 2; ni++)
                        mma_bf16(acc[c][mi][ni], af[mi], bfr[ni * 2], bfr[ni * 2 + 1]);
            }
        }
        __syncthreads();
    }

    // ---- rowsums -> inv norm (jg spans lane bits 0..2) ----
#pragma unroll
    for (int c = 0; c < 4; c++) {
        rs[c] += __shfl_xor_sync(0xFFFFFFFFu, rs[c], 1);
        rs[c] += __shfl_xor_sync(0xFFFFFFFFu, rs[c], 2);
        rs[c] += __shfl_xor_sync(0xFFFFFFFFu, rs[c], 4);
    }
    float* inv = reinterpret_cast<float*>(smem + INV_OFF);
    if (jg == 0) {
#pragma unroll
        for (int c = 0; c < 4; c++) inv[c * 64 + il] = 1.0f / (rs[c] + KEPS);
    }
    __syncthreads();

    // ---- epilogue ----
    const int g  = lane >> 2;
    const int qc = lane & 3;
#pragma unroll
    for (int mi = 0; mi < 2; mi++)
#pragma unroll
        for (int h = 0; h < 2; h++) {
            const int rl = wm * 32 + mi * 16 + g + h * 8;
            float iv[4];
#pragma unroll
            for (int c = 0; c < 4; c++) iv[c] = inv[c * 64 + rl];
#pragma unroll
            for (int ni = 0; ni < 2; ni++) {
                const int b = wn * 16 + ni * 8 + qc * 2;
                float v0 = 0.f, v1 = 0.f;
#pragma unroll
                for (int c = 0; c < 4; c++) {
                    v0 = fmaf(acc[c][mi][ni][h * 2 + 0], iv[c], v0);
                    v1 = fmaf(acc[c][mi][ni][h * 2 + 1], iv[c], v1);
                }
                const size_t o = (size_t)(s * KN + i0 + rl) * 128 + b;
                v0 += g_base[o];
                v1 += g_base[o + 1];
                out[o]     = tanhf(v0);
                out[o + 1] = tanhf(v1);
            }
        }
}

// ================================================================ launch
extern "C" void kernel_launch(void* const* d_in, const int* in_sizes, int n_in,
                              void* d_out, int out_size) {
    const float* A  = (const float*)d_in[0];
    const float* x  = (const float*)d_in[1];
    const float* w  = (const float*)d_in[2];
    const float* th = (const float*)d_in[3];
    float* out = (float*)d_out;
    (void)in_sizes; (void)n_in; (void)out_size;

    cudaFuncSetAttribute(main_kernel, cudaFuncAttributeMaxDynamicSharedMemorySize, SMEM_TOT);

    aux_kernel<<<1280, 256>>>(x, w, th);
    main_kernel<<<dim3(16, 16), 512, SMEM_TOT>>>(A, out);
}